// round 3
// baseline (speedup 1.0000x reference)
#include <cuda_runtime.h>
#include <cstdint>

#define NBLK 128
#define TPB  256
#define T_STEPS 512

// ---------------- persistent state (device globals; no allocation) ----------
__device__ float g_mem0[128 * 1024];
__device__ float g_mem1[128 * 1024];
__device__ float g_mem2[128 * 512];
__device__ float g_spk0[2][128 * 1024];
__device__ float g_spk1[2][128 * 1024];
__device__ float g_spk2[2][128 * 512];
__device__ unsigned g_arrive;
__device__ volatile unsigned g_epoch;

__global__ void snn_init_ctrl() { g_arrive = 0u; g_epoch = 0u; }

// ---------------- cp.async helpers -----------------------------------------
__device__ __forceinline__ void cpa4(uint32_t d, const float* s) {
    asm volatile("cp.async.ca.shared.global [%0], [%1], 4;" :: "r"(d), "l"(s));
}
// .cg (L2-only) is mandatory for spike reads: spike double-buffers reuse the
// same addresses every 2 ticks and are written by OTHER SMs; per-SM L1 would
// serve stale lines.
__device__ __forceinline__ void cpa16(uint32_t d, const float* s) {
    asm volatile("cp.async.cg.shared.global [%0], [%1], 16;" :: "r"(d), "l"(s));
}
__device__ __forceinline__ void cp_commit() { asm volatile("cp.async.commit_group;"); }
template <int W> __device__ __forceinline__ void cp_wait() {
    asm volatile("cp.async.wait_group %0;" :: "n"(W));
}

// ---------------- software grid barrier (128 co-resident blocks) ------------
__device__ __forceinline__ void grid_barrier(unsigned target) {
    __syncthreads();
    if (threadIdx.x == 0) {
        __threadfence();  // publish this block's spike/mem stores
        unsigned a = atomicAdd(&g_arrive, 1u);
        if (a == NBLK - 1u) {
            g_arrive = 0u;          // safe: everyone has arrived and is spinning
            __threadfence();
            atomicExch((unsigned*)&g_epoch, target);
        } else {
            while (*((volatile unsigned*)&g_epoch) < target) __nanosleep(64);
            __threadfence();        // acquire for subsequent L2 reads
        }
    }
    __syncthreads();
}

// ---------------- one 32x64 output tile of one layer at one timestep --------
// Single fp32 accumulator per output, k strictly ascending (bitwise matches a
// standard SIMT fp32 GEMM reduction). mem*0.5*(1-s) is exact (0.5 = 2^-1,
// s in {0,1}), so the only rounding is the FMA chain + one add, like the ref.
__device__ __forceinline__ void run_tile(
    const float* __restrict__ Asrc,  // spike buffer (row stride K), or inputs if gatherT >= 0
    int gatherT,                     // -1 => spike source; else timestep t for input gather
    const float* __restrict__ W, int K, int N,
    float* __restrict__ memArr,
    const float* __restrict__ spPrev,   // own layer spikes at t-1 (block-private)
    float* __restrict__ spCur,          // own layer spikes at t
    float* __restrict__ outp,           // final output (layer 2, t == 511) or null
    int m0, int n0,
    float (&As)[2][32][36], float (&Bs)[2][32][64])
{
    const int tid = threadIdx.x;
    const int lm = tid >> 3, lq = tid & 7;   // loader mapping
    const int tx = tid & 15, ty = tid >> 4;  // compute mapping: 16x16 threads, 2x4 micro-tile
    const uint32_t asB = (uint32_t)__cvta_generic_to_shared(&As[0][0][0]);
    const uint32_t bsB = (uint32_t)__cvta_generic_to_shared(&Bs[0][0][0]);
    const int nch = K >> 5;

    float acc[2][4];
#pragma unroll
    for (int r = 0; r < 2; r++)
#pragma unroll
        for (int c = 0; c < 4; c++) acc[r][c] = 0.0f;

    auto load_chunk = [&](int s, int c) {
        const int k0 = c << 5;
        // A tile: 32 rows x 32 k, stored As[m][k] (row padded to 36 floats:
        // 16B-aligned rows, bank-shift 4/row)
        uint32_t aD = asB + (uint32_t)(((s * 32 + lm) * 36 + lq * 4) * 4);
        if (gatherT >= 0) {
            // inputs[b][d][t]: stride-512 gather along d (k)
            const float* gp = Asrc + (size_t)(m0 + lm) * (512 * 512)
                                   + (size_t)(k0 + lq * 4) * 512 + gatherT;
            cpa4(aD, gp);
            cpa4(aD + 4u,  gp + 512);
            cpa4(aD + 8u,  gp + 1024);
            cpa4(aD + 12u, gp + 1536);
        } else {
            cpa16(aD, Asrc + (size_t)(m0 + lm) * K + (k0 + lq * 4));
        }
        // B tile: 32 k-rows x 64 n, Bs[k][n]
        const float* wb = W + (size_t)(k0 + lm) * N + n0;
        uint32_t bD = bsB + (uint32_t)(((s * 32 + lm) * 64 + lq * 4) * 4);
        cpa16(bD,        wb + lq * 4);
        cpa16(bD + 128u, wb + (lq + 8) * 4);
        cp_commit();
    };

    load_chunk(0, 0);
#pragma unroll 1
    for (int c = 0; c < nch; ++c) {
        const int s = c & 1;
        if (c + 1 < nch) { load_chunk(s ^ 1, c + 1); cp_wait<1>(); }
        else             { cp_wait<0>(); }
        __syncthreads();
#pragma unroll
        for (int k = 0; k < 32; k++) {
            float a0 = As[s][2 * ty + 0][k];
            float a1 = As[s][2 * ty + 1][k];
            float4 b = *reinterpret_cast<const float4*>(&Bs[s][k][tx * 4]);
            acc[0][0] = fmaf(a0, b.x, acc[0][0]);
            acc[0][1] = fmaf(a0, b.y, acc[0][1]);
            acc[0][2] = fmaf(a0, b.z, acc[0][2]);
            acc[0][3] = fmaf(a0, b.w, acc[0][3]);
            acc[1][0] = fmaf(a1, b.x, acc[1][0]);
            acc[1][1] = fmaf(a1, b.y, acc[1][1]);
            acc[1][2] = fmaf(a1, b.z, acc[1][2]);
            acc[1][3] = fmaf(a1, b.w, acc[1][3]);
        }
        __syncthreads();
    }

    // epilogue: leaky integrate + reset-by-spike + fire
#pragma unroll
    for (int r = 0; r < 2; r++) {
        const int m = m0 + 2 * ty + r;
#pragma unroll
        for (int cc = 0; cc < 4; cc++) {
            const int n = n0 + tx * 4 + cc;
            const int idx = m * N + n;
            float cur  = acc[r][cc];
            float sp   = spPrev[idx];         // block-private, L1-safe
            float mv   = memArr[idx];         // block-private, L1-safe
            float mnew = mv * 0.5f * (1.0f - sp) + cur;   // exact until the add
            float s    = (mnew > 0.3f) ? 1.0f : 0.0f;
            memArr[idx] = mnew;
            spCur[idx]  = s;
            if (outp) outp[idx] = s;
        }
    }
}

// ---------------- persistent pipelined kernel --------------------------------
// Tick tau: L0 computes step tau, L1 step tau-1, L2 step tau-2 (independent).
// 514 ticks, 1 grid barrier per tick.
__global__ void __launch_bounds__(TPB, 2)
snn_kernel(const float* __restrict__ xin,
           const float* __restrict__ w0,
           const float* __restrict__ w1,
           const float* __restrict__ w2,
           float* __restrict__ out)
{
    __shared__ __align__(16) float As[2][32][36];
    __shared__ __align__(16) float Bs[2][32][64];
    const int bid = blockIdx.x;

    // zero all state (both spike parities: t = -1 reads buffer parity 1)
    {
        const int stride = NBLK * TPB;
        const int i0 = bid * TPB + threadIdx.x;
        for (int i = i0; i < 128 * 1024; i += stride) {
            g_mem0[i] = 0.0f; g_mem1[i] = 0.0f;
            g_spk0[0][i] = 0.0f; g_spk0[1][i] = 0.0f;
            g_spk1[0][i] = 0.0f; g_spk1[1][i] = 0.0f;
        }
        for (int i = i0; i < 128 * 512; i += stride) {
            g_mem2[i] = 0.0f; g_spk2[0][i] = 0.0f; g_spk2[1][i] = 0.0f;
        }
    }
    grid_barrier(1u);

#pragma unroll 1
    for (int tick = 0; tick < T_STEPS + 2; ++tick) {
        if (bid < 64) {                       // layer 1: 4 x 16 tiles of 32x64
            const int t = tick - 1;
            if (t >= 0 && t < T_STEPS) {
                run_tile(g_spk0[t & 1], -1, w1, 1024, 1024,
                         g_mem1, g_spk1[(t - 1) & 1], g_spk1[t & 1], nullptr,
                         (bid >> 4) * 32, (bid & 15) * 64, As, Bs);
            }
        } else if (bid < 96) {                // layer 2: 4 x 8 tiles
            const int t = tick - 2;
            if (t >= 0 && t < T_STEPS) {
                const int id = bid - 64;
                run_tile(g_spk1[t & 1], -1, w2, 1024, 512,
                         g_mem2, g_spk2[(t - 1) & 1], g_spk2[t & 1],
                         (t == T_STEPS - 1) ? out : nullptr,
                         (id >> 3) * 32, (id & 7) * 64, As, Bs);
            }
        } else {                              // layer 0: two 32x64 tiles per block
            const int t = tick;
            if (t < T_STEPS) {
                const int i = bid - 96;
#pragma unroll 1
                for (int j = 0; j < 2; j++) {
                    const int id = 2 * i + j;
                    run_tile(xin, t, w0, 512, 1024,
                             g_mem0, g_spk0[(t - 1) & 1], g_spk0[t & 1], nullptr,
                             (id >> 4) * 32, (id & 15) * 64, As, Bs);
                }
            }
        }
        grid_barrier((unsigned)(tick + 2));
    }
}

extern "C" void kernel_launch(void* const* d_in, const int* in_sizes, int n_in,
                              void* d_out, int out_size)
{
    const float* xin = (const float*)d_in[0];   // inputs [128, 512, 512]
    const float* w0  = (const float*)d_in[1];   // [512, 1024]
    const float* w1  = (const float*)d_in[2];   // [1024, 1024]
    const float* w2  = (const float*)d_in[3];   // [1024, 512]
    float* out = (float*)d_out;                 // [128, 512]

    snn_init_ctrl<<<1, 1>>>();                  // reset barrier state every call
    snn_kernel<<<NBLK, TPB>>>(xin, w0, w1, w2, out);
}

// round 4
// speedup vs baseline: 1.0888x; 1.0888x over previous
#include <cuda_runtime.h>
#include <cstdint>

#define NBLK 128
#define TPB  256
#define T_STEPS 512
typedef unsigned long long ull;

// ---------------- persistent cross-layer spike buffers (transposed [d][b]) --
__device__ float g_s0T[2][1024 * 128];   // layer0 -> layer1 spikes
__device__ float g_s1T[2][1024 * 128];   // layer1 -> layer2 spikes
__device__ unsigned g_arrive;
__device__ volatile unsigned g_epoch;

__global__ void snn_init_ctrl() { g_arrive = 0u; g_epoch = 0u; }

// ---------------- PTX helpers ----------------------------------------------
__device__ __forceinline__ void cpa4(uint32_t d, const float* s) {
    asm volatile("cp.async.ca.shared.global [%0], [%1], 4;" :: "r"(d), "l"(s));
}
// .cg (L2-only): spike buffers are written by other SMs and reuse addresses
// every 2 ticks -> must bypass per-SM L1.
__device__ __forceinline__ void cpa16(uint32_t d, const float* s) {
    asm volatile("cp.async.cg.shared.global [%0], [%1], 16;" :: "r"(d), "l"(s));
}
__device__ __forceinline__ void cp_commit() { asm volatile("cp.async.commit_group;"); }
template <int W> __device__ __forceinline__ void cp_wait() {
    asm volatile("cp.async.wait_group %0;" :: "n"(W));
}
// packed fp32x2 FMA: each half is IEEE fp32 fma.rn -> bitwise identical to the
// scalar fmaf chain, at half the FMA-pipe issue slots.
__device__ __forceinline__ void fma2(ull& d, ull a, ull b) {
    asm volatile("fma.rn.f32x2 %0, %1, %2, %0;" : "+l"(d) : "l"(a), "l"(b));
}
__device__ __forceinline__ ull packrr(float x) {   // (x, x)
    ull r;
    asm("mov.b64 %0, {%1, %2};" : "=l"(r) : "f"(x), "f"(x));
    return r;
}
__device__ __forceinline__ void unpack2(float& lo, float& hi, ull v) {
    asm("mov.b64 {%0, %1}, %2;" : "=f"(lo), "=f"(hi) : "l"(v));
}

// ---------------- software grid barrier (128 co-resident blocks) ------------
__device__ __forceinline__ void grid_barrier(unsigned target) {
    __syncthreads();
    if (threadIdx.x == 0) {
        __threadfence();                      // publish spike stores
        unsigned a = atomicAdd(&g_arrive, 1u);
        if (a == NBLK - 1u) {
            g_arrive = 0u;
            __threadfence();
            atomicExch((unsigned*)&g_epoch, target);
        } else {
            while (*((volatile unsigned*)&g_epoch) < target) __nanosleep(64);
            __threadfence();                  // acquire
        }
    }
    __syncthreads();
}

// ---------------- one 32x64 output tile of one layer at one timestep --------
// A in smem k-major AsT[k][m] (32 floats/row), B n-major Bs[k][n].
// Thread = (warp mg: 4 rows m0+4*mg.., lane p: cols n0+2p, n0+2p+1).
// Rows packed pairwise into f32x2 accumulators; chain over k strictly
// ascending per output -> bitwise equal to reference fp32 FMA chain.
__device__ __forceinline__ void run_tile(
    const float* __restrict__ Asrc,  // spkT [k][128] buffer, or raw inputs if gatherT >= 0
    int gatherT,                     // -1 => spike source; else timestep for input gather
    const float* __restrict__ W, int K, int N,
    float (&mem)[8],                 // persistent membrane state (registers)
    float* __restrict__ spkT,        // transposed spike out [k][128] (or null)
    float* __restrict__ outp,        // final output [128][512] (or null)
    int m0, int n0,
    float (*AsT)[32], float (*Bs)[64])   // smem: [3*32][32], [3*32][64]
{
    const int tid = threadIdx.x;
    const int mg = tid >> 5, p = tid & 31;     // compute mapping
    const int lk = tid >> 3, lq = tid & 7;     // loader mapping (32 k x 8 quads)
    const int nch = K >> 5;
    const uint32_t aB = (uint32_t)__cvta_generic_to_shared(&AsT[0][0]);
    const uint32_t bB = (uint32_t)__cvta_generic_to_shared(&Bs[0][0]);

    auto load_chunk = [&](int st, int c) {
        const int k0 = c << 5;
        uint32_t ad = aB + (uint32_t)(((st * 32 + lk) * 32 + lq * 4) * 4);
        if (gatherT >= 0) {
            // inputs[b][d][t]: AsT[k][m] = inputs[m0+m][k0+k][t]
            const float* gp = Asrc + (size_t)(m0 + lq * 4) * (512 * 512)
                                   + (size_t)(k0 + lk) * 512 + gatherT;
            cpa4(ad,       gp);
            cpa4(ad + 4u,  gp + 262144);
            cpa4(ad + 8u,  gp + 524288);
            cpa4(ad + 12u, gp + 786432);
        } else {
            cpa16(ad, Asrc + (size_t)(k0 + lk) * 128 + m0 + lq * 4);
        }
        const float* wb = W + (size_t)(k0 + lk) * N + n0;
        uint32_t bd = bB + (uint32_t)(((st * 32 + lk) * 64 + lq * 4) * 4);
        cpa16(bd,         wb + lq * 4);
        cpa16(bd + 128u,  wb + (lq + 8) * 4);
        cp_commit();
    };

    ull acc00 = 0ull, acc01 = 0ull, acc10 = 0ull, acc11 = 0ull;

    load_chunk(0, 0);
    load_chunk(1, 1);
    cp_wait<1>();
    __syncthreads();

#pragma unroll 1
    for (int c = 0; c < nch; ++c) {
        const int st = c % 3;
        if (c + 2 < nch) load_chunk((c + 2) % 3, c + 2);
        const float* As_ = &AsT[st * 32][0];
        const float* Bs_ = &Bs[st * 32][0];
#pragma unroll
        for (int k = 0; k < 32; ++k) {
            ulonglong2 av = *reinterpret_cast<const ulonglong2*>(As_ + k * 32 + mg * 4);
            float2 bv = *reinterpret_cast<const float2*>(Bs_ + k * 64 + p * 2);
            ull b00 = packrr(bv.x);
            ull b11 = packrr(bv.y);
            fma2(acc00, av.x, b00);
            fma2(acc01, av.y, b00);
            fma2(acc10, av.x, b11);
            fma2(acc11, av.y, b11);
        }
        if (c + 2 < nch) cp_wait<1>(); else cp_wait<0>();
        __syncthreads();
    }

    // epilogue: leaky integrate + reset-by-spike + fire (all in registers)
    float cur[4][2];
    unpack2(cur[0][0], cur[1][0], acc00);
    unpack2(cur[2][0], cur[3][0], acc01);
    unpack2(cur[0][1], cur[1][1], acc10);
    unpack2(cur[2][1], cur[3][1], acc11);

    float s[4][2];
#pragma unroll
    for (int r = 0; r < 4; r++)
#pragma unroll
        for (int cc = 0; cc < 2; cc++) {
            float mv = mem[r * 2 + cc];
            float keep = (mv > 0.3f) ? 0.0f : 0.5f;       // prev spike derived from mem
            float mnew = fmaf(mv, keep, cur[r][cc]);      // mv*0.5 exact -> bitwise == ref
            mem[r * 2 + cc] = mnew;
            s[r][cc] = (mnew > 0.3f) ? 1.0f : 0.0f;
        }

    if (spkT) {
#pragma unroll
        for (int cc = 0; cc < 2; cc++) {
            float4 v = make_float4(s[0][cc], s[1][cc], s[2][cc], s[3][cc]);
            *reinterpret_cast<float4*>(spkT + (size_t)(n0 + p * 2 + cc) * 128 + m0 + mg * 4) = v;
        }
    }
    if (outp) {
#pragma unroll
        for (int r = 0; r < 4; r++) {
            float2 v = make_float2(s[r][0], s[r][1]);
            *reinterpret_cast<float2*>(outp + (size_t)(m0 + mg * 4 + r) * 512 + n0 + p * 2) = v;
        }
    }
}

// ---------------- persistent pipelined kernel --------------------------------
// Tick tau: L0 computes step tau, L1 step tau-1, L2 step tau-2 (independent).
// One grid barrier per tick; membrane state lives in registers for the whole run.
__global__ void __launch_bounds__(TPB, 1)
snn_kernel(const float* __restrict__ xin,
           const float* __restrict__ w0,
           const float* __restrict__ w1,
           const float* __restrict__ w2,
           float* __restrict__ out)
{
    __shared__ __align__(16) float AsT[3 * 32][32];
    __shared__ __align__(16) float Bs[3 * 32][64];
    const int bid = blockIdx.x;

    float memA[8], memB[8];
#pragma unroll
    for (int i = 0; i < 8; i++) { memA[i] = 0.0f; memB[i] = 0.0f; }

#pragma unroll 1
    for (int tick = 0; tick < T_STEPS + 2; ++tick) {
        if (bid < 64) {                       // layer 1: 4 x 16 tiles of 32x64
            const int t = tick - 1;
            if (t >= 0 && t < T_STEPS) {
                run_tile(g_s0T[t & 1], -1, w1, 1024, 1024, memA,
                         g_s1T[t & 1], nullptr,
                         (bid >> 4) * 32, (bid & 15) * 64, AsT, Bs);
            }
        } else if (bid < 96) {                // layer 2: 4 x 8 tiles
            const int t = tick - 2;
            if (t >= 0 && t < T_STEPS) {
                const int id = bid - 64;
                run_tile(g_s1T[t & 1], -1, w2, 1024, 512, memA,
                         nullptr, (t == T_STEPS - 1) ? out : nullptr,
                         (id >> 3) * 32, (id & 7) * 64, AsT, Bs);
            }
        } else {                              // layer 0: two 32x64 tiles per block
            const int t = tick;
            if (t < T_STEPS) {
                const int i = bid - 96;
                {
                    const int id = 2 * i;
                    run_tile(xin, t, w0, 512, 1024, memA, g_s0T[t & 1], nullptr,
                             (id >> 4) * 32, (id & 15) * 64, AsT, Bs);
                }
                {
                    const int id = 2 * i + 1;
                    run_tile(xin, t, w0, 512, 1024, memB, g_s0T[t & 1], nullptr,
                             (id >> 4) * 32, (id & 15) * 64, AsT, Bs);
                }
            }
        }
        grid_barrier((unsigned)(tick + 1));
    }
}

extern "C" void kernel_launch(void* const* d_in, const int* in_sizes, int n_in,
                              void* d_out, int out_size)
{
    const float* xin = (const float*)d_in[0];   // inputs [128, 512, 512]
    const float* w0  = (const float*)d_in[1];   // [512, 1024]
    const float* w1  = (const float*)d_in[2];   // [1024, 1024]
    const float* w2  = (const float*)d_in[3];   // [1024, 512]
    float* out = (float*)d_out;                 // [128, 512]

    snn_init_ctrl<<<1, 1>>>();                  // reset barrier state every replay
    snn_kernel<<<NBLK, TPB>>>(xin, w0, w1, w2, out);
}